// round 17
// baseline (speedup 1.0000x reference)
#include <cuda_runtime.h>
#include <cuda_fp16.h>
#include <cstdint>

// LSTM B=8192, T=128, I=32, H=64, OUT=8.
// R17: R7 math (fp16 m16n8k16 / fp32 acc, fp32 tanh.approx, frag-major
// LDS.128, 2-group interleaved pipeline) restructured as HALF-SIZE CTAs:
// M_BLK=32 (2 groups x 16 rows), 128 threads (4 warps x n=16 cols),
// 2 CTAs per SM (launch_bounds(128,2), grid=256). Independent co-resident
// CTAs fill each other's barrier/dependency gaps on every SMSP.

#define B_TOT 8192
#define T_LEN 128
#define I_SZ  32
#define H_SZ  64
#define OUT_SZ 8
#define M_BLK 32
#define NTHREADS 128

__device__ __forceinline__ uint32_t packh2(float a, float b) {
    __half2 h = __floats2half2_rn(a, b);   // .x = a (low)
    return *reinterpret_cast<uint32_t*>(&h);
}
__device__ __forceinline__ float tanhhw(float x) {
    float y;
    asm("tanh.approx.f32 %0, %1;" : "=f"(y) : "f"(x));
    return y;
}
__device__ __forceinline__ void mma_f16(float c[4],
                                        uint32_t a0, uint32_t a1, uint32_t a2, uint32_t a3,
                                        uint32_t b0, uint32_t b1) {
    asm("mma.sync.aligned.m16n8k16.row.col.f32.f16.f16.f32 "
        "{%0,%1,%2,%3},{%4,%5,%6,%7},{%8,%9},{%0,%1,%2,%3};"
        : "+f"(c[0]), "+f"(c[1]), "+f"(c[2]), "+f"(c[3])
        : "r"(a0), "r"(a1), "r"(a2), "r"(a3), "r"(b0), "r"(b1));
}

// one q-slice: LDS.128 of the (16-row x k16) A fragment + 8 MMAs (4 gates x 2 n-tiles)
__device__ __forceinline__ void frag8(float (&acc)[2][4][4], const uint32_t* __restrict__ blk,
                                      int lane, const uint32_t (&bfr)[4][6][2][2], int q) {
    uint4 av = *reinterpret_cast<const uint4*>(blk + lane * 4);
    #pragma unroll
    for (int g = 0; g < 4; ++g) {
        mma_f16(acc[0][g], av.x, av.y, av.z, av.w, bfr[g][q][0][0], bfr[g][q][0][1]);
        mma_f16(acc[1][g], av.x, av.y, av.z, av.w, bfr[g][q][1][0], bfr[g][q][1][1]);
    }
}

// activate 4 elems of one n-tile; i/f/o pre-scaled by 0.5 (sigmoid = 0.5*tanh+0.5)
__device__ __forceinline__ void act_r(const float acc[4][4], float cst[4], float hv[4]) {
    #pragma unroll
    for (int e = 0; e < 4; ++e) {
        float ig = fmaf(tanhhw(acc[0][e]), 0.5f, 0.5f);
        float fg = fmaf(tanhhw(acc[1][e]), 0.5f, 0.5f);
        float gg = tanhhw(acc[2][e]);
        float og = fmaf(tanhhw(acc[3][e]), 0.5f, 0.5f);
        float c  = fg * cst[e] + ig * gg;
        cst[e] = c;
        hv[e] = og * tanhhw(c);
    }
}

// Phase: mma(group GM) into accM; act(accA -> h of group GA); stage x(GA,t+1).
template <int GM, int GA>
__device__ __forceinline__ void phase_fn(uint32_t* __restrict__ Xs, uint32_t* __restrict__ Hs,
                                         float (&accM)[2][4][4], float (&accA)[2][4][4],
                                         float (&cst)[2][4], float4& xr,
                                         const float* __restrict__ xga, int t, int lane,
                                         int xoff0, int xoff1, int hoff,
                                         const uint32_t (&bfr)[4][6][2][2],
                                         const float (&bias2)[4][2][2]) {
    const uint32_t* Xm = Xs + GM * 256;
    const uint32_t* Hm = Hs + GM * 512;

    #pragma unroll
    for (int nt = 0; nt < 2; ++nt)
        #pragma unroll
        for (int g = 0; g < 4; ++g) {
            accM[nt][g][0] = bias2[g][nt][0];
            accM[nt][g][1] = bias2[g][nt][1];
            accM[nt][g][2] = bias2[g][nt][0];
            accM[nt][g][3] = bias2[g][nt][1];
        }

    float hv0[4], hv1[4];

    // x-part (q=0..1) interleaved with act nt=0
    frag8(accM, Xm + 0,   lane, bfr, 0);
    act_r(accA[0], cst[0], hv0);
    frag8(accM, Xm + 128, lane, bfr, 1);

    // h-part (q=2..5) interleaved with act nt=1 + staging
    frag8(accM, Hm + 0,   lane, bfr, 2);
    act_r(accA[1], cst[1], hv1);
    frag8(accM, Hm + 128, lane, bfr, 3);

    // stage x(GA, t+1) + prefetch x(GA, t+2)
    {
        uint32_t* Xa = Xs + GA * 256;
        Xa[xoff0] = packh2(xr.x, xr.y);
        Xa[xoff1] = packh2(xr.z, xr.w);
        int tt = (t + 2 < T_LEN) ? t + 2 : T_LEN - 1;
        xr = *reinterpret_cast<const float4*>(xga + (size_t)tt * I_SZ);
    }

    frag8(accM, Hm + 256, lane, bfr, 4);

    // h(GA) writeback: ONE STS.128 — thread's 4 h-words are its own lane slot
    // in frag-major H block w (warp's 16 cols == block w).
    {
        uint32_t* Ha = Hs + GA * 512;
        *reinterpret_cast<uint4*>(Ha + hoff) =
            make_uint4(packh2(hv0[0], hv0[1]), packh2(hv0[2], hv0[3]),
                       packh2(hv1[0], hv1[1]), packh2(hv1[2], hv1[3]));
    }

    frag8(accM, Hm + 384, lane, bfr, 5);
}

__global__ __launch_bounds__(NTHREADS, 2)
void lstm_fp16_kernel(const float* __restrict__ x,
                      const float* __restrict__ W_ih,
                      const float* __restrict__ W_hh,
                      const float* __restrict__ b_ih,
                      const float* __restrict__ b_hh,
                      const float* __restrict__ W_fc,
                      const float* __restrict__ b_fc,
                      float* __restrict__ out) {
    __shared__ __align__(16) uint32_t Xs[2 * 256];   // per group: 2 frag blocks (k 0..31)
    __shared__ __align__(16) uint32_t Hs[2 * 512];   // per group: 4 frag blocks (h cols)

    const int tid  = threadIdx.x;
    const int warp = tid >> 5;     // 0..3, owns gate-cols w*16..w*16+15 per gate
    const int lane = tid & 31;
    const int row0 = blockIdx.x * M_BLK;
    const int arl  = lane >> 2;
    const int akl  = lane & 3;

    // ---- B fragments: [gate][q][ntile][2], fp16 half2; i/f/o pre-scaled by 0.5 ----
    uint32_t bfr[4][6][2][2];
    float bias2[4][2][2];
    {
        #pragma unroll
        for (int g = 0; g < 4; ++g) {
            const float s = (g == 2) ? 1.0f : 0.5f;
            #pragma unroll
            for (int nt = 0; nt < 2; ++nt) {
                const int gc = g * 64 + warp * 16 + nt * 8 + arl;
                #pragma unroll
                for (int q = 0; q < 6; ++q) {
                    const int k0 = q * 16 + 2 * akl;
                    float w[4];
                    #pragma unroll
                    for (int j = 0; j < 4; ++j) {
                        const int k = k0 + ((j < 2) ? j : j + 6);   // k0,k0+1,k0+8,k0+9
                        w[j] = (k < I_SZ) ? W_ih[gc * I_SZ + k] : W_hh[gc * H_SZ + (k - I_SZ)];
                    }
                    bfr[g][q][nt][0] = packh2(w[0] * s, w[1] * s);
                    bfr[g][q][nt][1] = packh2(w[2] * s, w[3] * s);
                }
                const int c0 = g * 64 + warp * 16 + nt * 8 + 2 * akl;
                bias2[g][nt][0] = (b_ih[c0] + b_hh[c0]) * s;
                bias2[g][nt][1] = (b_ih[c0 + 1] + b_hh[c0 + 1]) * s;
            }
        }
    }

    // zero H tiles (h0 = 0)
    for (int i = tid; i < 2 * 512; i += NTHREADS) Hs[i] = 0u;

    // h writeback offset: warp's 16 cols form frag block 'warp'; lane slot is its own
    const int hoff = warp * 128 + lane * 4;

    // ---- x staging: one float4 -> two half2 words per thread per group ----
    const int srow = tid >> 3;           // 0..15
    const int scol = (tid & 7) * 4;      // 0,4,...,28
    int xoff0, xoff1;
    {
        const int qx   = scol >> 4;                       // frag block 0/1
        const int pl   = (scol >> 1) & 3;                 // kpair low 2 bits
        const int word = ((scol & 15) >> 3) * 2 + ((srow >> 3) & 1);
        xoff0 = qx * 128 + ((srow & 7) * 4 + pl) * 4 + word;
        xoff1 = xoff0 + 4;                                // adjacent lane slot, same word
    }
    const float* xga0 = x + ((size_t)(row0 + srow) * T_LEN) * I_SZ + scol;
    const float* xga1 = x + ((size_t)(row0 + 16 + srow) * T_LEN) * I_SZ + scol;

    float4 xr0, xr1;
    {
        float4 v0 = *reinterpret_cast<const float4*>(xga0);
        float4 v1 = *reinterpret_cast<const float4*>(xga1);
        Xs[xoff0]       = packh2(v0.x, v0.y);
        Xs[xoff1]       = packh2(v0.z, v0.w);
        Xs[256 + xoff0] = packh2(v1.x, v1.y);
        Xs[256 + xoff1] = packh2(v1.z, v1.w);
        xr0 = *reinterpret_cast<const float4*>(xga0 + I_SZ);
        xr1 = *reinterpret_cast<const float4*>(xga1 + I_SZ);
    }

    float acc0[2][4][4], acc1[2][4][4];
    float cst0[2][4] = {}, cst1[2][4] = {};

    __syncthreads();

    // prologue: gates(G0, 0) -> acc0
    {
        #pragma unroll
        for (int nt = 0; nt < 2; ++nt)
            #pragma unroll
            for (int g = 0; g < 4; ++g) {
                acc0[nt][g][0] = bias2[g][nt][0];
                acc0[nt][g][1] = bias2[g][nt][1];
                acc0[nt][g][2] = bias2[g][nt][0];
                acc0[nt][g][3] = bias2[g][nt][1];
            }
        frag8(acc0, Xs + 0,   lane, bfr, 0);
        frag8(acc0, Xs + 128, lane, bfr, 1);
        #pragma unroll
        for (int qh = 0; qh < 4; ++qh)
            frag8(acc0, Hs + qh * 128, lane, bfr, 2 + qh);
    }
    __syncthreads();

    for (int t = 0; t < T_LEN; ++t) {
        phase_fn<1, 0>(Xs, Hs, acc1, acc0, cst0, xr0, xga0, t, lane,
                       xoff0, xoff1, hoff, bfr, bias2);
        __syncthreads();
        phase_fn<0, 1>(Xs, Hs, acc0, acc1, cst1, xr1, xga1, t, lane,
                       xoff0, xoff1, hoff, bfr, bias2);
        __syncthreads();
    }

    // ---- FC epilogue: gather h_T from frag-major fp16 tiles ----
    for (int idx = tid; idx < M_BLK * OUT_SZ; idx += NTHREADS) {
        const int row = idx >> 3;         // 0..31
        const int o   = idx & 7;
        const int g   = row >> 4;
        const int lr  = row & 15;
        const uint32_t* Hg = Hs + g * 512;
        const float* wf = W_fc + o * H_SZ;
        float s = b_fc[o];
        #pragma unroll
        for (int cc = 0; cc < 32; ++cc) {
            const int c  = cc * 2;
            const int qh = c >> 4;
            const int p  = (c & 15) >> 1;
            uint32_t wv = Hg[qh * 128 + ((lr & 7) * 4 + (p & 3)) * 4
                             + (p >> 2) * 2 + ((lr >> 3) & 1)];
            __half2 h2 = *reinterpret_cast<__half2*>(&wv);
            float2 f2 = __half22float2(h2);
            s += f2.x * wf[c] + f2.y * wf[c + 1];
        }
        out[(size_t)(row0 + row) * OUT_SZ + o] = s;
    }
}

extern "C" void kernel_launch(void* const* d_in, const int* in_sizes, int n_in,
                              void* d_out, int out_size) {
    const float* x    = (const float*)d_in[0];
    const float* W_ih = (const float*)d_in[1];
    const float* W_hh = (const float*)d_in[2];
    const float* b_ih = (const float*)d_in[3];
    const float* b_hh = (const float*)d_in[4];
    const float* W_fc = (const float*)d_in[5];
    const float* b_fc = (const float*)d_in[6];
    float* out = (float*)d_out;

    lstm_fp16_kernel<<<B_TOT / M_BLK, NTHREADS>>>(x, W_ih, W_hh, b_ih, b_hh, W_fc, b_fc, out);
}